// round 17
// baseline (speedup 1.0000x reference)
#include <cuda_runtime.h>
#include <cuda_bf16.h>

// Problem constants
#define Bn   8
#define Tn   4
#define HIDn 4096
#define Hn   32
#define Dn   128
#define SCn  4096          // cache length
#define SFn  4100          // cache + T
#define BT   32            // B*T
#define KSPLIT 8
#define KCHUNK (HIDn / KSPLIT)   // 512
#define NSPLIT 16          // cache splits (256 rows each)
#define PART_N 17          // 16 cache splits + 1 new-token slot (warps merged in-block)

// attn bulk pipeline
#define CH_ROWS 4                       // rows per chunk
#define CSTAGES 4                       // ring depth (chunks)
#define NCHUNK  (64 / CH_ROWS)          // 16 chunks per warp
#define CHUNK_B (CH_ROWS * Dn * 4)      // 2048 B per tensor per chunk
#define SLOT_F  (2 * CH_ROWS * Dn)      // floats per slot (k+v)
#define WARP_F  (CSTAGES * SLOT_F)      // floats per warp ring
#define ATTN_DSMEM (4 * WARP_F * 4)     // 65536 bytes dynamic smem

#define OUT_K_OFF   ((size_t)131072)                       // out elems
#define KFULL_ELEMS ((size_t)Bn * Hn * SFn * Dn)           // 134,348,800

// ---------------- scratch (no allocations allowed) ----------------
__device__ float g_qkv_part[3 * KSPLIT * BT * HIDn];   // split-K partials for q,k,v proj
__device__ float g_q[Bn * Hn * Tn * Dn];               // RoPE'd q, [b,h,t,d]
__device__ float g_pm[Bn * Hn * PART_N * Tn];          // per-partial running max (log2 domain)
__device__ float g_pl[Bn * Hn * PART_N * Tn];          // per-partial running denom
__device__ float g_pacc[Bn * Hn * PART_N * Tn * Dn];   // per-partial weighted V acc
__device__ float g_o[BT * HIDn];                       // attention out, [b*T+t, h*D+d]
__device__ float g_opart[KSPLIT * BT * HIDn];          // split-K partials for Wo gemm

// ---------------- f32x2 packed-FMA helpers (Blackwell FFMA2) ----------------
#define FMA2(d, a, b, c) \
    asm("fma.rn.f32x2 %0, %1, %2, %3;" : "=l"(d) : "l"(a), "l"(b), "l"(c))
#define PACK2BC(d, x) \
    asm("mov.b64 %0, {%1, %1};" : "=l"(d) : "r"(__float_as_uint(x)))
#define UNPACK2(lo, hi, p) \
    asm("mov.b64 {%0, %1}, %2;" : "=f"(lo), "=f"(hi) : "l"(p))

// ---------------- bulk-async (TMA engine) helpers ----------------
#define MBAR_INIT(mb, cnt) \
    asm volatile("mbarrier.init.shared.b64 [%0], %1;" :: "r"(mb), "r"(cnt) : "memory")
#define MBAR_EXPECT_TX(mb, bytes) \
    asm volatile("mbarrier.arrive.expect_tx.shared.b64 _, [%0], %1;" \
                 :: "r"(mb), "r"(bytes) : "memory")
#define MBAR_WAIT(mb, parity) do {                                          \
    asm volatile("{\n\t.reg .pred P;\n\t"                                   \
        "W%=: mbarrier.try_wait.parity.acquire.cta.shared::cta.b64 P, [%0], %1, 0x989680;\n\t" \
        "@P bra D%=;\n\t bra W%=;\n\tD%=:\n\t}"                             \
        :: "r"(mb), "r"(parity) : "memory");                                \
} while (0)
#define BULK_LD(smem, gmem, bytes, mb) \
    asm volatile("cp.async.bulk.shared::cta.global.mbarrier::complete_tx::bytes [%0], [%1], %2, [%3];" \
                 :: "r"(smem), "l"(gmem), "r"(bytes), "r"(mb) : "memory")
#define BULK_ST(gmem, smem, bytes) \
    asm volatile("cp.async.bulk.global.shared::cta.bulk_group [%0], [%1], %2;" \
                 :: "l"(gmem), "r"(smem), "r"(bytes) : "memory")
#define BULK_COMMIT() asm volatile("cp.async.bulk.commit_group;" ::: "memory")
#define BULK_WAIT_READ0() \
    asm volatile("cp.async.bulk.wait_group.read 0;" ::: "memory")
#define BULK_WAIT_WRITE0() \
    asm volatile("cp.async.bulk.wait_group 0;" ::: "memory")

// streaming-cache helpers
__device__ __forceinline__ void stcs4(float* p, float4 v) { __stcs((float4*)p, v); }

// ---------------- GEMM: Y[m,n] = sum_k X[m,k] * W[n,k] ----------------
// M=32, K=4096, N=4096. Block 256 threads computes [32m x 128n] over a
// KCHUNK k-range. Smem-tiled, coalesced global loads, XOR-swizzled W tile
// (conflict-free transpose STS + compute LDS.128), f32x2 packed FMA inner loop.
__global__ void __launch_bounds__(256) gemm32(
        const float* __restrict__ X,   // nullptr -> use g_o
        const float* __restrict__ W0,
        const float* __restrict__ W1,
        const float* __restrict__ W2) {
    __shared__ __align__(16) float Xs[32][36];   // [k][m], 16B-aligned rows, conflict-free STS
    __shared__ float Ws[32][132];                // [k][swizzled n], stride 132 -> conflict-free

    const float* Xp = X ? X : g_o;
    float* part = X ? g_qkv_part : g_opart;
    int mat = blockIdx.z;
    const float* W = (mat == 0) ? W0 : (mat == 1 ? W1 : W2);

    int tid = threadIdx.x;
    int lk = tid & 7;        // float4 index along k for loads (0..7)
    int lm = tid >> 3;       // row index for loads (0..31)
    int ng = tid & 31;       // n-group in compute (0..31) -> cols ng*4..+3
    int mg = tid >> 5;       // m-group / warp id (0..7)  -> rows mg*4..+3

    int n0blk = blockIdx.x * 128;
    int k0 = blockIdx.y * KCHUNK;

    unsigned long long acc[2][4];   // [m-pair][n], each is f32x2 (m0,m1)
#pragma unroll
    for (int i = 0; i < 2; i++)
#pragma unroll
        for (int j = 0; j < 4; j++) acc[i][j] = 0ull;

    const float* xg = Xp + (size_t)lm * HIDn + k0 + lk * 4;
    const float* wg = W + (size_t)(n0blk + lm) * HIDn + k0 + lk * 4;

    for (int kt = 0; kt < KCHUNK; kt += 32) {
        // --- load X tile [32m x 32k], store transposed ---
        float4 xv = *(const float4*)(xg + kt);
        Xs[lk * 4 + 0][lm] = xv.x;
        Xs[lk * 4 + 1][lm] = xv.y;
        Xs[lk * 4 + 2][lm] = xv.z;
        Xs[lk * 4 + 3][lm] = xv.w;
        // --- load W tile [128n x 32k], store transposed + XOR swizzle ---
#pragma unroll
        for (int it = 0; it < 4; it++) {
            int n = lm + it * 32;
            float4 wv = *(const float4*)(wg + (size_t)(it * 32) * HIDn + kt);
            int c = (((n >> 2) ^ lk) << 2) + (n & 3);
            Ws[lk * 4 + 0][c] = wv.x;
            Ws[lk * 4 + 1][c] = wv.y;
            Ws[lk * 4 + 2][c] = wv.z;
            Ws[lk * 4 + 3][c] = wv.w;
        }
        __syncthreads();

#pragma unroll
        for (int kk = 0; kk < 32; kk++) {
            int k4 = kk >> 2;
            // x pairs via one 128-bit shared load (broadcast across warp)
            ulonglong2 xp = *(const ulonglong2*)&Xs[kk][mg * 4];
            // w: de-swizzled LDS.128 (ng^k4 is a lane permutation -> conflict-free)
            float4 wv = *(const float4*)&Ws[kk][((ng ^ k4) << 2)];
            unsigned long long wb0, wb1, wb2, wb3;
            PACK2BC(wb0, wv.x); PACK2BC(wb1, wv.y);
            PACK2BC(wb2, wv.z); PACK2BC(wb3, wv.w);
            FMA2(acc[0][0], xp.x, wb0, acc[0][0]);
            FMA2(acc[0][1], xp.x, wb1, acc[0][1]);
            FMA2(acc[0][2], xp.x, wb2, acc[0][2]);
            FMA2(acc[0][3], xp.x, wb3, acc[0][3]);
            FMA2(acc[1][0], xp.y, wb0, acc[1][0]);
            FMA2(acc[1][1], xp.y, wb1, acc[1][1]);
            FMA2(acc[1][2], xp.y, wb2, acc[1][2]);
            FMA2(acc[1][3], xp.y, wb3, acc[1][3]);
        }
        __syncthreads();
    }

    // epilogue: thread owns rows mg*4..mg*4+3, cols n0blk + ng*4..+3
    float* pp = part + ((size_t)(mat * KSPLIT + blockIdx.y) * BT) * HIDn + n0blk + ng * 4;
#pragma unroll
    for (int mp = 0; mp < 2; mp++) {
        float lo[4], hi[4];
#pragma unroll
        for (int j = 0; j < 4; j++) UNPACK2(lo[j], hi[j], acc[mp][j]);
        *(float4*)(pp + (size_t)(mg * 4 + 2 * mp) * HIDn) =
            make_float4(lo[0], lo[1], lo[2], lo[3]);
        *(float4*)(pp + (size_t)(mg * 4 + 2 * mp + 1) * HIDn) =
            make_float4(hi[0], hi[1], hi[2], hi[3]);
    }
}

// ---------------- RoPE + scatter new k/v into d_out, q into scratch ----------------
__global__ void rope_scatter(const float* __restrict__ cs, const float* __restrict__ sn,
                             float* __restrict__ out) {
    int idx = blockIdx.x * blockDim.x + threadIdx.x;  // < 131072
    int d = idx & 127;
    int h = (idx >> 7) & 31;
    int t = (idx >> 12) & 3;
    int b = idx >> 14;
    int row = b * Tn + t;
    int col = h * Dn + d;
    int col2 = h * Dn + ((d + 64) & 127);

    float q = 0.f, k = 0.f, v = 0.f, q2 = 0.f, k2 = 0.f;
#pragma unroll
    for (int kz = 0; kz < KSPLIT; kz++) {
        size_t r = (size_t)row * HIDn;
        q  += __ldcs(&g_qkv_part[(size_t)(kz)              * BT * HIDn + r + col]);
        q2 += __ldcs(&g_qkv_part[(size_t)(kz)              * BT * HIDn + r + col2]);
        k  += __ldcs(&g_qkv_part[(size_t)(KSPLIT + kz)     * BT * HIDn + r + col]);
        k2 += __ldcs(&g_qkv_part[(size_t)(KSPLIT + kz)     * BT * HIDn + r + col2]);
        v  += __ldcs(&g_qkv_part[(size_t)(2 * KSPLIT + kz) * BT * HIDn + r + col]);
    }
    float sgn = (d < 64) ? -1.f : 1.f;   // rotate_half: [-x[64:], x[:64]]
    float c = cs[row * Dn + d];
    float s = sn[row * Dn + d];
    float qr = q * c + sgn * q2 * s;
    float kr = k * c + sgn * k2 * s;

    g_q[((size_t)(b * Hn + h) * Tn + t) * Dn + d] = qr;
    size_t ko = OUT_K_OFF + ((size_t)(b * Hn + h) * SFn + SCn + t) * Dn + d;
    out[ko] = kr;                 // k_full new row
    out[ko + KFULL_ELEMS] = v;    // v_full new row (no RoPE on v)
}

// online-softmax update for one k/v row (scores in log2 domain)
__device__ __forceinline__ void online_row(const float4 kc, const float4 vc,
                                           const float4 qf[4],
                                           float m[4], float l[4], float4 acc[4]) {
    const float sc = 0.088388347648318447f * 1.4426950408889634f;  // 1/sqrt(128) * log2(e)
    float p[4];
#pragma unroll
    for (int t = 0; t < 4; t++)
        p[t] = qf[t].x * kc.x + qf[t].y * kc.y + qf[t].z * kc.z + qf[t].w * kc.w;
#pragma unroll
    for (int off = 16; off; off >>= 1) {
#pragma unroll
        for (int t = 0; t < 4; t++)
            p[t] += __shfl_xor_sync(0xffffffffu, p[t], off);
    }
#pragma unroll
    for (int t = 0; t < 4; t++) {
        float s = p[t] * sc;
        if (s > m[t]) {                       // lazy rescale: rare after warmup
            float f = exp2f(m[t] - s);
            m[t] = s;
            l[t] *= f;
            acc[t].x *= f; acc[t].y *= f; acc[t].z *= f; acc[t].w *= f;
        }
        float e = exp2f(s - m[t]);
        l[t] += e;
        acc[t].x += e * vc.x; acc[t].y += e * vc.y;
        acc[t].z += e * vc.z; acc[t].w += e * vc.w;
    }
}

// ---------------- fused cache copy + flash-decode partial attention ----------------
// grid (17, H, B), block 128 (4 warps). splits 0..15: 256 cache rows each.
// Per-warp 4-deep ring of 4-row chunks: bulk-async (TMA) loads gmem->smem with
// mbarrier completion; the cache->k_full/v_full copy is a bulk-async store
// issued BEFORE consuming the chunk (no per-lane STG); compute reads smem via
// LDS.128 only. Warps' online-softmax states merged in-block -> 1 partial slot.
__global__ void __launch_bounds__(128) attn_copy(
        const float* __restrict__ ck, const float* __restrict__ cv, float* out) {
    extern __shared__ __align__(16) float dyn[];    // 4 warps * CSTAGES * (k 2KB + v 2KB)
    __shared__ float s_m[4][4];            // [warp][t]
    __shared__ float s_l[4][4];
    __shared__ float4 s_acc[3][4][32];     // warps 1..3: [warp-1][t][lane]
    __shared__ __align__(8) unsigned long long mbar[4][CSTAGES];

    int split = blockIdx.x;
    int h = blockIdx.y, b = blockIdx.z;
    int bh = b * Hn + h;
    int wid = threadIdx.x >> 5, lane = threadIdx.x & 31;

    float4 qf[4];
#pragma unroll
    for (int t = 0; t < 4; t++)
        qf[t] = *(const float4*)&g_q[((size_t)bh * Tn + t) * Dn + lane * 4];

    float m[4], l[4];
    float4 acc[4];
#pragma unroll
    for (int t = 0; t < 4; t++) { m[t] = -1e30f; l[t] = 0.f; acc[t] = make_float4(0, 0, 0, 0); }

    if (split < NSPLIT) {
        int s0 = split * 256 + wid * 64;
        const float* kg = ck + ((size_t)bh * SCn + s0) * Dn;
        const float* vg = cv + ((size_t)bh * SCn + s0) * Dn;
        float* kout = out + OUT_K_OFF + ((size_t)bh * SFn + s0) * Dn;
        float* vout = kout + KFULL_ELEMS;

        float* wring = dyn + wid * WARP_F;
        unsigned ring0 = (unsigned)__cvta_generic_to_shared(wring);
        unsigned mb0 = (unsigned)__cvta_generic_to_shared(&mbar[wid][0]);

        if (lane == 0) {
#pragma unroll
            for (int s = 0; s < CSTAGES; s++) MBAR_INIT(mb0 + s * 8, 1);
        }
        __syncwarp();
        if (lane == 0) {
#pragma unroll
            for (int c = 0; c < CSTAGES; c++) {   // prologue: fill the ring
                unsigned slot = ring0 + c * (SLOT_F * 4);
                MBAR_EXPECT_TX(mb0 + c * 8, 2 * CHUNK_B);
                BULK_LD(slot,             kg + (size_t)c * CH_ROWS * Dn, CHUNK_B, mb0 + c * 8);
                BULK_LD(slot + CHUNK_B,   vg + (size_t)c * CH_ROWS * Dn, CHUNK_B, mb0 + c * 8);
            }
        }

        for (int c = 0; c < NCHUNK; c++) {
            int st = c & (CSTAGES - 1);
            unsigned slotu = ring0 + st * (SLOT_F * 4);
            float* slot = wring + st * SLOT_F;
            MBAR_WAIT(mb0 + st * 8, (c >> 2) & 1);

            // copy chunk -> k_full/v_full via bulk store (TMA engine reads smem)
            if (lane == 0) {
                BULK_ST(kout + (size_t)c * CH_ROWS * Dn, slotu,           CHUNK_B);
                BULK_ST(vout + (size_t)c * CH_ROWS * Dn, slotu + CHUNK_B, CHUNK_B);
                BULK_COMMIT();
            }

            // consume 4 rows (lane-private LDS.128, conflict-free)
#pragma unroll
            for (int r = 0; r < CH_ROWS; r++) {
                float4 kc = *(const float4*)&slot[r * Dn + lane * 4];
                float4 vc = *(const float4*)&slot[CH_ROWS * Dn + r * Dn + lane * 4];
                online_row(kc, vc, qf, m, l, acc);
            }
            __syncwarp();   // all lanes done reading slot before refill

            int nc = c + CSTAGES;
            if (nc < NCHUNK && lane == 0) {
                BULK_WAIT_READ0();   // this slot's store has been read out of smem
                MBAR_EXPECT_TX(mb0 + st * 8, 2 * CHUNK_B);
                BULK_LD(slotu,           kg + (size_t)nc * CH_ROWS * Dn, CHUNK_B, mb0 + st * 8);
                BULK_LD(slotu + CHUNK_B, vg + (size_t)nc * CH_ROWS * Dn, CHUNK_B, mb0 + st * 8);
            }
        }
        if (lane == 0) BULK_WAIT_WRITE0();   // all copy writes durable before exit
    } else {
        // new rows already written to d_out by rope_scatter; read back, no copy
        const float* kr = out + OUT_K_OFF + ((size_t)bh * SFn + SCn + wid) * Dn + lane * 4;
        float4 kc = *(const float4*)kr;
        float4 vc = *(const float4*)(kr + KFULL_ELEMS);
        online_row(kc, vc, qf, m, l, acc);
    }

    // ---- in-block merge of the 4 warps' online-softmax states ----
    if (lane == 0) {
#pragma unroll
        for (int t = 0; t < 4; t++) { s_m[wid][t] = m[t]; s_l[wid][t] = l[t]; }
    }
    if (wid > 0) {
#pragma unroll
        for (int t = 0; t < 4; t++) s_acc[wid - 1][t][lane] = acc[t];
    }
    __syncthreads();

    if (wid == 0) {
        size_t base = ((size_t)bh * PART_N + split) * Tn;
#pragma unroll
        for (int t = 0; t < 4; t++) {
            float m0 = s_m[0][t], m1 = s_m[1][t], m2 = s_m[2][t], m3 = s_m[3][t];
            float M = fmaxf(fmaxf(m0, m1), fmaxf(m2, m3));
            float f0 = exp2f(m0 - M), f1 = exp2f(m1 - M);
            float f2 = exp2f(m2 - M), f3 = exp2f(m3 - M);
            float L = f0 * s_l[0][t] + f1 * s_l[1][t] + f2 * s_l[2][t] + f3 * s_l[3][t];
            float4 a1 = s_acc[0][t][lane], a2 = s_acc[1][t][lane], a3 = s_acc[2][t][lane];
            float4 A;
            A.x = f0 * acc[t].x + f1 * a1.x + f2 * a2.x + f3 * a3.x;
            A.y = f0 * acc[t].y + f1 * a1.y + f2 * a2.y + f3 * a3.y;
            A.z = f0 * acc[t].z + f1 * a1.z + f2 * a2.z + f3 * a3.z;
            A.w = f0 * acc[t].w + f1 * a1.w + f2 * a2.w + f3 * a3.w;
            if (lane == 0) { g_pm[base + t] = M; g_pl[base + t] = L; }
            *(float4*)&g_pacc[(base + t) * Dn + lane * 4] = A;
        }
    }
}

// ---------------- combine split partials -> attention output ----------------
// grid 256 (one block per bh), block 128: warp w handles t=w, lanes over d.
__global__ void combine_splits() {
    int bh = blockIdx.x;
    int b = bh >> 5, h = bh & 31;
    int t = threadIdx.x >> 5, lane = threadIdx.x & 31;
    size_t base = (size_t)bh * PART_N * Tn;

    // per-t softmax-merge scalars (broadcast loads within warp)
    float mx = -1e30f;
#pragma unroll
    for (int p = 0; p < PART_N; p++)
        mx = fmaxf(mx, g_pm[base + (size_t)p * Tn + t]);
    float den = 0.f;
    float e[PART_N];
#pragma unroll
    for (int p = 0; p < PART_N; p++) {
        e[p] = exp2f(g_pm[base + (size_t)p * Tn + t] - mx);
        den += g_pl[base + (size_t)p * Tn + t] * e[p];
    }

    float4 num = make_float4(0, 0, 0, 0);
#pragma unroll
    for (int p = 0; p < PART_N; p++) {
        float4 a = *(const float4*)&g_pacc[(base + (size_t)p * Tn + t) * Dn + lane * 4];
        num.x += e[p] * a.x; num.y += e[p] * a.y;
        num.z += e[p] * a.z; num.w += e[p] * a.w;
    }
    float inv = 1.f / den;
    float4 o = make_float4(num.x * inv, num.y * inv, num.z * inv, num.w * inv);
    *(float4*)&g_o[(size_t)(b * Tn + t) * HIDn + h * Dn + lane * 4] = o;
}

// ---------------- sum Wo split-K partials into final out ----------------
__global__ void finalize(float* __restrict__ out) {
    int idx = blockIdx.x * blockDim.x + threadIdx.x;  // < 131072
    float s = 0.f;
#pragma unroll
    for (int kz = 0; kz < KSPLIT; kz++)
        s += __ldcs(&g_opart[(size_t)kz * BT * HIDn + idx]);
    out[idx] = s;
}

extern "C" void kernel_launch(void* const* d_in, const int* in_sizes, int n_in,
                              void* d_out, int out_size) {
    const float* hidden  = (const float*)d_in[0];
    const float* cache_k = (const float*)d_in[1];
    const float* cache_v = (const float*)d_in[2];
    const float* cosp    = (const float*)d_in[3];
    const float* sinp    = (const float*)d_in[4];
    const float* Wq      = (const float*)d_in[5];
    const float* Wk      = (const float*)d_in[6];
    const float* Wv      = (const float*)d_in[7];
    const float* Wo      = (const float*)d_in[8];
    float* out = (float*)d_out;

    static int smem_set = 0;
    if (!smem_set) {
        cudaFuncSetAttribute(attn_copy, cudaFuncAttributeMaxDynamicSharedMemorySize,
                             ATTN_DSMEM);
        smem_set = 1;
    }

    // 1) QKV projections (split-K partials)
    gemm32<<<dim3(32, KSPLIT, 3), 256>>>(hidden, Wq, Wk, Wv);
    // 2) reduce split-K + RoPE + scatter new k/v rows into d_out, q into scratch
    rope_scatter<<<512, 256>>>(cosp, sinp, out);
    // 3) fused cache copy + flash-decode partials (bulk-async pipelined)
    attn_copy<<<dim3(NSPLIT + 1, Hn, Bn), 128, ATTN_DSMEM>>>(cache_k, cache_v, out);
    // 4) combine partials
    combine_splits<<<Bn * Hn, 128>>>();
    // 5) output projection (split-K partials, X = g_o selected by nullptr)
    gemm32<<<dim3(32, KSPLIT, 1), 256>>>(nullptr, Wo, Wo, Wo);
    // 6) reduce into d_out
    finalize<<<512, 256>>>(out);
}